// round 14
// baseline (speedup 1.0000x reference)
#include <cuda_runtime.h>
#include <math_constants.h>

#define NB 256
#define NQ 1000
#define NC 80
#define NN 80000          // NQ * NC per batch
#define TOPK 300
#define NT 512            // select kernel threads (2 keys/thread)
#define ST 256            // stream kernel threads
#define NCHS 5            // chunks per batch (stream)
#define SCHS 16384        // elements per chunk (2 rounds of 8 float4/thread)
#define CHCAP 1024        // per-chunk survivor slice capacity
#define SORTN 1024        // bitonic sort size (positions)
#define FBCAP 6144        // fallback gmem candidate cap
#define THRF 2.42f        // fixed stream threshold (~620 survivors/batch on N(0,1));
                          // m<300 or m>1024 triggers the exact fallback path

// ---------------- global scratch (static __device__, no allocs) ----------------
__device__ unsigned long long g_bufc[NB][NCHS][CHCAP];  // per-chunk survivor slices
__device__ int g_cntc[NB][NCHS];                        // per-chunk counts (plain stores)
__device__ unsigned long long g_fb[NB][FBCAP];          // fallback candidates (cold)

// ---------- monotone float<->uint mapping ----------
__device__ __forceinline__ unsigned flipf(unsigned b) {
    return (b & 0x80000000u) ? ~b : (b | 0x80000000u);
}
__device__ __forceinline__ unsigned unflipf(unsigned u) {
    return (u & 0x80000000u) ? (u & 0x7FFFFFFFu) : ~u;
}

// ---------- sigmoid matching XLA: logistic(x) = 0.5 + 0.5*tanh(0.5*x) ----------
__device__ __forceinline__ float sigmoid_ref(float x) {
    float hx = __fmul_rn(0.5f, x);
    float ax = fabsf(hx);
    float xc = fminf(fmaxf(hx, -9.0f), 9.0f);
    float x2 = __fmul_rn(xc, xc);
    float p = -2.76076847742355e-16f;
    p = fmaf(x2, p, 2.00018790482477e-13f);
    p = fmaf(x2, p, -8.60467152213735e-11f);
    p = fmaf(x2, p, 5.12229709037114e-08f);
    p = fmaf(x2, p, 1.48572235717979e-05f);
    p = fmaf(x2, p, 6.37261928875436e-04f);
    p = fmaf(x2, p, 4.89352455891786e-03f);
    p = __fmul_rn(xc, p);
    float q = 1.19825839466702e-06f;
    q = fmaf(x2, q, 1.18534705686654e-04f);
    q = fmaf(x2, q, 2.26843463243900e-03f);
    q = fmaf(x2, q, 4.89352518554385e-03f);
    float t = __fdiv_rn(p, q);
    t = (ax < 4e-4f) ? hx : t;
    return __fadd_rn(__fmul_rn(0.5f, t), 0.5f);
}

// ---------- output writer (labels / boxes / scores regions) ----------
__device__ __forceinline__ void write_result(float* __restrict__ out,
                                             const float* __restrict__ boxes,
                                             int b, int r, unsigned long long k) {
    unsigned idx = 0xFFFFFFFFu - (unsigned)k;
    float s = __uint_as_float((unsigned)(k >> 32));
    int q = (int)(idx / NC);
    int c = (int)(idx - (unsigned)q * NC);
    size_t o = (size_t)b * TOPK + (size_t)r;
    out[o] = (float)c;                                   // labels
    float4 bx = *reinterpret_cast<const float4*>(
        boxes + ((size_t)b * NQ + (size_t)q) * 4);
    float4 xy;
    xy.x = bx.x - 0.5f * bx.z;
    xy.y = bx.y - 0.5f * bx.w;
    xy.z = bx.x + 0.5f * bx.z;
    xy.w = bx.y + 0.5f * bx.w;
    *reinterpret_cast<float4*>(out + (size_t)NB * TOPK + o * 4) = xy;  // boxes
    out[(size_t)NB * TOPK * 5 + o] = s;                  // scores
}

// ================= kernel B: lean full-bandwidth filter stream =================
extern "C" __global__ void __launch_bounds__(ST, 4)
stream_kernel(const float* __restrict__ logits) {
    __shared__ unsigned long long skeys[CHCAP];
    __shared__ int s_cnt;

    const int tid = threadIdx.x;
    const int lane = tid & 31;
    const int chunk = blockIdx.x;          // 0..NCHS-1
    const int b = blockIdx.y;              // 0..NB-1
    const float* Lp = logits + (size_t)b * NN + chunk * SCHS;
    const int rem = NN - chunk * SCHS;
    const unsigned ltmask = (1u << lane) - 1u;

    if (tid == 0) s_cnt = 0;
    __syncthreads();

    #pragma unroll
    for (int rd = 0; rd < 2; ++rd) {       // 2 rounds x 8 in-flight LDG.128
        const int robase = rd * (ST * 4 * 8);
        float4 v[8];
        bool ok[8];
        #pragma unroll
        for (int i = 0; i < 8; ++i) {
            int off = robase + i * (ST * 4) + tid * 4;
            ok[i] = off < rem;
            if (ok[i]) v[i] = __ldcs(reinterpret_cast<const float4*>(Lp + off));
        }
        #pragma unroll
        for (int i = 0; i < 8; ++i) {
            float4 w = v[i];
            float gmax = ok[i] ? fmaxf(fmaxf(w.x, w.y), fmaxf(w.z, w.w)) : -CUDART_INF_F;
            if (__any_sync(0xFFFFFFFFu, gmax >= THRF)) {
                int base = chunk * SCHS + robase + i * (ST * 4) + tid * 4;
                bool c0 = ok[i] && (w.x >= THRF);
                bool c1 = ok[i] && (w.y >= THRF);
                bool c2 = ok[i] && (w.z >= THRF);
                bool c3 = ok[i] && (w.w >= THRF);
                unsigned m0 = __ballot_sync(0xFFFFFFFFu, c0);
                unsigned m1 = __ballot_sync(0xFFFFFFFFu, c1);
                unsigned m2 = __ballot_sync(0xFFFFFFFFu, c2);
                unsigned m3 = __ballot_sync(0xFFFFFFFFu, c3);
                int tot = __popc(m0) + __popc(m1) + __popc(m2) + __popc(m3);
                int wb = 0;
                if (lane == 0) wb = atomicAdd(&s_cnt, tot);
                wb = __shfl_sync(0xFFFFFFFFu, wb, 0);
                int p = wb;
                if (c0) {
                    int ix = p + __popc(m0 & ltmask);
                    if (ix < CHCAP) skeys[ix] = ((unsigned long long)flipf(__float_as_uint(w.x)) << 32) | (unsigned)base;
                }
                p += __popc(m0);
                if (c1) {
                    int ix = p + __popc(m1 & ltmask);
                    if (ix < CHCAP) skeys[ix] = ((unsigned long long)flipf(__float_as_uint(w.y)) << 32) | (unsigned)(base + 1);
                }
                p += __popc(m1);
                if (c2) {
                    int ix = p + __popc(m2 & ltmask);
                    if (ix < CHCAP) skeys[ix] = ((unsigned long long)flipf(__float_as_uint(w.z)) << 32) | (unsigned)(base + 2);
                }
                p += __popc(m2);
                if (c3) {
                    int ix = p + __popc(m3 & ltmask);
                    if (ix < CHCAP) skeys[ix] = ((unsigned long long)flipf(__float_as_uint(w.w)) << 32) | (unsigned)(base + 3);
                }
            }
        }
    }
    __syncthreads();
    const int cn = s_cnt;
    for (int i = tid; i < min(cn, CHCAP); i += ST)
        g_bufc[b][chunk][i] = skeys[i];
    if (tid == 0) g_cntc[b][chunk] = cn;      // raw count (overflow detect)
}

// ================= kernel C: gather+sigmoid -> 2-key hybrid bitonic -> write =================
extern "C" __global__ void __launch_bounds__(NT)
select_kernel(const float* __restrict__ logits,
              const float* __restrict__ boxes,
              float* __restrict__ out) {
    __shared__ unsigned long long lst[SORTN];    // 8 KB
    __shared__ int s_off[NCHS + 1];
    __shared__ int s_bad;
    __shared__ int s_cnt;

    const int tid = threadIdx.x;
    const int lane = tid & 31;
    const int wid = tid >> 5;                 // 16 warps
    const int b = blockIdx.x;

    if (tid < NCHS) s_off[tid] = g_cntc[b][tid];
    __syncthreads();
    if (tid == 0) {
        int acc = 0, bd = 0;
        for (int s2 = 0; s2 < NCHS; ++s2) {
            int c = s_off[s2];
            if (c > CHCAP) { bd = 1; c = CHCAP; }
            s_off[s2] = acc;
            acc += c;
        }
        s_off[NCHS] = acc;
        s_bad = bd || (acc > SORTN) || (acc < TOPK);
    }
    __syncthreads();

    if (!s_bad) {
        // ---- fused gather + sigmoid rank-key build (16 warps, 3 parts/slice) ----
        const int msel = s_off[NCHS];
        for (int s2 = wid; s2 < NCHS * 3; s2 += 16) {
            int sl = s2 % NCHS;
            int part = s2 / NCHS;                               // 0..2
            int o0 = s_off[sl];
            int len = s_off[sl + 1] - o0;
            for (int i = part * 32 + lane; i < len; i += 96) {
                unsigned long long k = g_bufc[b][sl][i];
                unsigned u = (unsigned)(k >> 32);
                unsigned idx = (unsigned)k;
                float s = sigmoid_ref(__uint_as_float(unflipf(u)));
                lst[o0 + i] = ((unsigned long long)__float_as_uint(s) << 32) |
                              (unsigned)(0xFFFFFFFFu - idx);
            }
        }
        __syncthreads();
        for (int i = msel + tid; i < SORTN; i += NT) lst[i] = 0ull;  // pad: smallest
        __syncthreads();

        // ---- hybrid bitonic sort, 2 keys/thread (positions tid and tid+NT) ----
        unsigned long long c0 = lst[tid];
        unsigned long long c1 = lst[tid + NT];
        const int p0 = tid, p1 = tid + NT;
        #pragma unroll
        for (int k = 2; k <= SORTN; k <<= 1) {
            #pragma unroll
            for (int j = k >> 1; j > 0; j >>= 1) {
                if (j >= NT) {
                    // j == NT: partner of p0 is p1 (local register exchange)
                    bool km0 = (((p0 & k) == 0) == ((p0 & j) == 0));
                    bool gt = c1 > c0;
                    unsigned long long lo = gt ? c0 : c1;
                    unsigned long long hi = gt ? c1 : c0;
                    if (km0) { c0 = hi; c1 = lo; } else { c0 = lo; c1 = hi; }
                } else if (j >= 32) {
                    lst[p0] = c0; lst[p1] = c1;
                    __syncthreads();
                    unsigned long long q0 = lst[p0 ^ j];
                    unsigned long long q1 = lst[p1 ^ j];
                    __syncthreads();
                    bool km0 = (((p0 & k) == 0) == ((p0 & j) == 0));
                    bool km1 = (((p1 & k) == 0) == ((p1 & j) == 0));
                    c0 = (km0 == (q0 > c0)) ? q0 : c0;
                    c1 = (km1 == (q1 > c1)) ? q1 : c1;
                } else {
                    unsigned long long q0 = __shfl_xor_sync(0xFFFFFFFFu, c0, j);
                    unsigned long long q1 = __shfl_xor_sync(0xFFFFFFFFu, c1, j);
                    bool km0 = (((p0 & k) == 0) == ((p0 & j) == 0));
                    bool km1 = (((p1 & k) == 0) == ((p1 & j) == 0));
                    c0 = (km0 == (q0 > c0)) ? q0 : c0;
                    c1 = (km1 == (q1 > c1)) ? q1 : c1;
                }
            }
        }
        if (tid < TOPK) write_result(out, boxes, b, tid, c0);
        return;
    }

    // ================= fallback (never taken normally): exact bit-radix =================
    // Find max threshold T (in flipped-uint space) with count(>=T) >= TOPK, collect,
    // then O(m^2) rank. Slow but exact; handles any data the fast path rejects.
    const float* Lb = logits + (size_t)b * NN;
    unsigned prefix = 0u;
    for (int bit = 31; bit >= 0; --bit) {
        unsigned cand = prefix | (1u << bit);
        __syncthreads();
        if (tid == 0) s_cnt = 0;
        __syncthreads();
        int local = 0;
        for (int i = tid; i < NN; i += NT)
            if (flipf(__float_as_uint(Lb[i])) >= cand) local++;
        #pragma unroll
        for (int o = 16; o > 0; o >>= 1) local += __shfl_down_sync(0xFFFFFFFFu, local, o);
        if (lane == 0) atomicAdd(&s_cnt, local);
        __syncthreads();
        if (s_cnt >= TOPK) prefix = cand;   // uniform decision (post-barrier read)
    }
    __syncthreads();
    if (tid == 0) s_cnt = 0;
    __syncthreads();
    for (int i = tid; i < NN; i += NT) {
        unsigned ub = flipf(__float_as_uint(Lb[i]));
        if (ub >= prefix) {
            int p = atomicAdd(&s_cnt, 1);
            if (p < FBCAP) {
                float s = sigmoid_ref(__uint_as_float(unflipf(ub)));
                g_fb[b][p] = ((unsigned long long)__float_as_uint(s) << 32) |
                             (unsigned)(0xFFFFFFFFu - (unsigned)i);
            }
        }
    }
    __syncthreads();
    int m2 = min(s_cnt, FBCAP);
    for (int i = tid; i < m2; i += NT) {
        unsigned long long k = g_fb[b][i];
        int r = 0;
        for (int j = 0; j < m2; ++j) r += (g_fb[b][j] > k) ? 1 : 0;
        if (r < TOPK) write_result(out, boxes, b, r, k);
    }
}

extern "C" void kernel_launch(void* const* d_in, const int* in_sizes, int n_in,
                              void* d_out, int out_size) {
    const float* logits = (const float*)d_in[0];
    const float* boxes = (const float*)d_in[1];
    dim3 sg(NCHS, NB, 1);
    stream_kernel<<<sg, ST>>>(logits);
    select_kernel<<<NB, NT>>>(logits, boxes, (float*)d_out);
}